// round 1
// baseline (speedup 1.0000x reference)
#include <cuda_runtime.h>
#include <cstdint>

#define B_  4
#define T_  2048
#define D_  1024
#define H_  16
#define HD_ 64

// Scratch (static device globals -- allocation-free per harness rules)
__device__ float g_q[(size_t)B_*H_*T_*HD_];   // [b,h,t,hd]
__device__ float g_k[(size_t)B_*H_*T_*HD_];
__device__ float g_v[(size_t)B_*H_*T_*HD_];
__device__ float g_ao[(size_t)B_*T_*D_];      // attention output, [b,t,d]

// fp32 -> tf32 with round-to-nearest (RNA). Truncation would bias sums ~1e-3.
__device__ __forceinline__ unsigned f2tf(float f){
    unsigned u; asm("cvt.rna.tf32.f32 %0, %1;" : "=r"(u) : "f"(f)); return u;
}

// m16n8k8 tf32 MMA, fp32 accumulate
__device__ __forceinline__ void mma8(float* d, const unsigned* a, const unsigned* b){
    asm volatile("mma.sync.aligned.m16n8k8.row.col.f32.tf32.tf32.f32 "
        "{%0,%1,%2,%3},{%4,%5,%6,%7},{%8,%9},{%0,%1,%2,%3};\n"
        : "+f"(d[0]), "+f"(d[1]), "+f"(d[2]), "+f"(d[3])
        : "r"(a[0]), "r"(a[1]), "r"(a[2]), "r"(a[3]), "r"(b[0]), "r"(b[1]));
}

// ---------------------------------------------------------------------------
// GEMM: C[m,n] = sum_k X[m,k] * W[n,k]   (both row-major, K contiguous: "NT")
// mode 0: X = x, W selected by blockIdx.z in {Wq,Wk,Wv}; epilogue writes
//         head-major scratch g_q/g_k/g_v.
// mode 1: X = g_ao, W = W0 (=Wo); epilogue adds bias, writes outF ([b,t,d]).
// Tiles: BM=128, BN=128, BK=32; 256 threads, warp tile 32x64.
// ---------------------------------------------------------------------------
__global__ void __launch_bounds__(256)
gemm_tf32(const float* __restrict__ X,
          const float* __restrict__ W0, const float* __restrict__ W1,
          const float* __restrict__ W2,
          float* __restrict__ outF, const float* __restrict__ bias,
          int mode)
{
    __shared__ unsigned As[128][36];   // pad 4 -> (4g+c)%32 conflict-free frags
    __shared__ unsigned Bs[128][36];

    const int tid  = threadIdx.x;
    const int lane = tid & 31;
    const int warp = tid >> 5;
    const int g = lane >> 2, c = lane & 3;
    const int wr = warp & 3, wc = warp >> 2;     // 4x2 warp grid
    const int m0 = blockIdx.y * 128;
    const int n0 = blockIdx.x * 128;

    const float* Xp = (mode == 0) ? X : g_ao;
    const float* W  = W0;
    if (mode == 0) { if (blockIdx.z == 1) W = W1; else if (blockIdx.z == 2) W = W2; }

    float acc[2][8][4];
    #pragma unroll
    for (int i=0;i<2;i++)
        #pragma unroll
        for (int j=0;j<8;j++)
            #pragma unroll
            for (int q2=0;q2<4;q2++) acc[i][j][q2] = 0.f;

    const int lr = tid >> 3;          // 0..31
    const int lc = (tid & 7) << 2;    // 0,4,...,28

    // Prefetch tile 0 into registers
    float4 pa[4], pb[4];
    #pragma unroll
    for (int i=0;i<4;i++){
        pa[i] = *(const float4*)(Xp + (size_t)(m0 + lr + 32*i)*1024 + lc);
        pb[i] = *(const float4*)(W  + (size_t)(n0 + lr + 32*i)*1024 + lc);
    }

    for (int kt = 0; kt < 32; kt++){
        // Commit prefetched tile to smem (tf32-rounded)
        #pragma unroll
        for (int i=0;i<4;i++){
            uint4 ua = make_uint4(f2tf(pa[i].x), f2tf(pa[i].y), f2tf(pa[i].z), f2tf(pa[i].w));
            *(uint4*)&As[lr + 32*i][lc] = ua;
            uint4 ub = make_uint4(f2tf(pb[i].x), f2tf(pb[i].y), f2tf(pb[i].z), f2tf(pb[i].w));
            *(uint4*)&Bs[lr + 32*i][lc] = ub;
        }
        __syncthreads();

        // Issue next tile's global loads (latency hidden under compute)
        if (kt + 1 < 32){
            const int ko = (kt + 1) * 32;
            #pragma unroll
            for (int i=0;i<4;i++){
                pa[i] = *(const float4*)(Xp + (size_t)(m0 + lr + 32*i)*1024 + ko + lc);
                pb[i] = *(const float4*)(W  + (size_t)(n0 + lr + 32*i)*1024 + ko + lc);
            }
        }

        #pragma unroll
        for (int ks = 0; ks < 4; ks++){
            unsigned af[2][4], bf[8][2];
            #pragma unroll
            for (int mt=0; mt<2; mt++){
                const int row = wr*32 + mt*16;
                af[mt][0] = As[row+g  ][ks*8 + c];
                af[mt][1] = As[row+g+8][ks*8 + c];
                af[mt][2] = As[row+g  ][ks*8 + c + 4];
                af[mt][3] = As[row+g+8][ks*8 + c + 4];
            }
            #pragma unroll
            for (int nt=0; nt<8; nt++){
                const int row = wc*64 + nt*8 + g;
                bf[nt][0] = Bs[row][ks*8 + c];
                bf[nt][1] = Bs[row][ks*8 + c + 4];
            }
            #pragma unroll
            for (int mt=0; mt<2; mt++)
                #pragma unroll
                for (int nt=0; nt<8; nt++)
                    mma8(acc[mt][nt], af[mt], bf[nt]);
        }
        __syncthreads();
    }

    // Epilogue
    float* outp = outF;
    if (mode == 0) outp = (blockIdx.z == 0) ? g_q : (blockIdx.z == 1) ? g_k : g_v;

    #pragma unroll
    for (int mt=0; mt<2; mt++){
        #pragma unroll
        for (int half=0; half<2; half++){
            const int r = m0 + wr*32 + mt*16 + g + half*8;   // global m = b*T + t
            #pragma unroll
            for (int nt=0; nt<8; nt++){
                const int n = n0 + wc*64 + nt*8 + 2*c;       // e = h*64 + hd (even)
                const float v0 = acc[mt][nt][half*2];
                const float v1 = acc[mt][nt][half*2 + 1];
                if (mode == 0){
                    const int b = r >> 11, t = r & (T_ - 1);
                    const int h = n >> 6, hd = n & 63;
                    *(float2*)(outp + ((size_t)((b*H_ + h)*T_ + t) << 6) + hd)
                        = make_float2(v0, v1);
                } else {
                    const float2 bb = *(const float2*)(bias + n);
                    *(float2*)(outp + (size_t)r*D_ + n)
                        = make_float2(v0 + bb.x, v1 + bb.y);
                }
            }
        }
    }
}

// ---------------------------------------------------------------------------
// Causal flash attention. Block = 128 threads (4 warps) handles one (b,h) and
// a 64-row Q block. Per-array XOR swizzles keep every fragment load pattern
// bank-conflict-free while fitting 3x 16KB tiles in exactly 48KB static smem.
// ---------------------------------------------------------------------------
__device__ __forceinline__ int sw2(int row, int col){ return col ^ ((row & 7) << 2); }
__device__ __forceinline__ int sw3(int row, int col){ return col ^ ((row & 7) << 3); }

__global__ void __launch_bounds__(128)
attn_tf32()
{
    __shared__ unsigned Qs[64][64];   // Q tile; reused as P tile after frag build
    __shared__ unsigned Ks[64][64];
    __shared__ unsigned Vs[64][64];

    const int qb  = blockIdx.x;       // 0..31 query block
    const int bh  = blockIdx.y;       // 0..63 = b*H + h
    const int tid = threadIdx.x;
    const int lane = tid & 31, warp = tid >> 5;
    const int g = lane >> 2, c = lane & 3;

    const float* Qg = g_q + (size_t)bh * (T_*HD_);
    const float* Kg = g_k + (size_t)bh * (T_*HD_);
    const float* Vg = g_v + (size_t)bh * (T_*HD_);

    const int lr = tid >> 4;          // 0..7
    const int lc = (tid & 15) << 2;   // 0..60

    // Load Q block, pre-scaled by 1/sqrt(HD)=0.125 (exact power of 2)
    #pragma unroll
    for (int i=0;i<8;i++){
        const int row = lr + 8*i;
        const float4 v = *(const float4*)(Qg + (size_t)(qb*64 + row)*64 + lc);
        const int pc = sw2(row, lc);
        Qs[row][pc+0] = f2tf(v.x * 0.125f);
        Qs[row][pc+1] = f2tf(v.y * 0.125f);
        Qs[row][pc+2] = f2tf(v.z * 0.125f);
        Qs[row][pc+3] = f2tf(v.w * 0.125f);
    }
    __syncthreads();

    // Cache Q A-fragments in registers (8 k-steps x 4 regs)
    unsigned qa[8][4];
    {
        const int r0 = warp*16 + g, r1 = r0 + 8;
        #pragma unroll
        for (int ks=0;ks<8;ks++){
            qa[ks][0] = Qs[r0][sw2(r0, ks*8 + c)];
            qa[ks][1] = Qs[r1][sw2(r1, ks*8 + c)];
            qa[ks][2] = Qs[r0][sw2(r0, ks*8 + c + 4)];
            qa[ks][3] = Qs[r1][sw2(r1, ks*8 + c + 4)];
        }
    }
    __syncthreads();   // all warps done reading Qs before it becomes P scratch

    float o[8][4];
    #pragma unroll
    for (int nt=0;nt<8;nt++){ o[nt][0]=o[nt][1]=o[nt][2]=o[nt][3]=0.f; }
    float mrow0 = -1e30f, mrow1 = -1e30f, lrow0 = 0.f, lrow1 = 0.f;

    for (int j = 0; j <= qb; j++){
        // Load K,V blocks (tf32-rounded)
        #pragma unroll
        for (int i=0;i<8;i++){
            const int row = lr + 8*i;
            const float4 kv = *(const float4*)(Kg + (size_t)(j*64 + row)*64 + lc);
            const int pk = sw2(row, lc);
            Ks[row][pk+0]=f2tf(kv.x); Ks[row][pk+1]=f2tf(kv.y);
            Ks[row][pk+2]=f2tf(kv.z); Ks[row][pk+3]=f2tf(kv.w);
            const float4 vv = *(const float4*)(Vg + (size_t)(j*64 + row)*64 + lc);
            const int pv = sw3(row, lc);
            Vs[row][pv+0]=f2tf(vv.x); Vs[row][pv+1]=f2tf(vv.y);
            Vs[row][pv+2]=f2tf(vv.z); Vs[row][pv+3]=f2tf(vv.w);
        }
        __syncthreads();

        // S = (Q/8) @ K^T
        float s[8][4];
        #pragma unroll
        for (int nt=0;nt<8;nt++){ s[nt][0]=s[nt][1]=s[nt][2]=s[nt][3]=0.f; }
        #pragma unroll
        for (int ks=0;ks<8;ks++){
            #pragma unroll
            for (int nt=0;nt<8;nt++){
                const int row = nt*8 + g;
                unsigned bb[2] = { Ks[row][sw2(row, ks*8 + c)],
                                   Ks[row][sw2(row, ks*8 + c + 4)] };
                mma8(s[nt], qa[ks], bb);
            }
        }

        const int r0 = warp*16 + g, r1 = r0 + 8;

        // Causal mask (only the diagonal block needs it)
        if (j == qb){
            #pragma unroll
            for (int nt=0;nt<8;nt++){
                const int col = nt*8 + 2*c;
                if (col     > r0) s[nt][0] = -1e30f;
                if (col + 1 > r0) s[nt][1] = -1e30f;
                if (col     > r1) s[nt][2] = -1e30f;
                if (col + 1 > r1) s[nt][3] = -1e30f;
            }
        }

        // Online softmax: row max / exp / row sum (quad shfl reductions)
        float mx0 = -1e30f, mx1 = -1e30f;
        #pragma unroll
        for (int nt=0;nt<8;nt++){
            mx0 = fmaxf(mx0, fmaxf(s[nt][0], s[nt][1]));
            mx1 = fmaxf(mx1, fmaxf(s[nt][2], s[nt][3]));
        }
        mx0 = fmaxf(mx0, __shfl_xor_sync(0xffffffffu, mx0, 1));
        mx0 = fmaxf(mx0, __shfl_xor_sync(0xffffffffu, mx0, 2));
        mx1 = fmaxf(mx1, __shfl_xor_sync(0xffffffffu, mx1, 1));
        mx1 = fmaxf(mx1, __shfl_xor_sync(0xffffffffu, mx1, 2));

        const float mn0 = fmaxf(mrow0, mx0), mn1 = fmaxf(mrow1, mx1);
        const float al0 = __expf(mrow0 - mn0), al1 = __expf(mrow1 - mn1);
        float sum0 = 0.f, sum1 = 0.f;
        #pragma unroll
        for (int nt=0;nt<8;nt++){
            s[nt][0] = __expf(s[nt][0] - mn0);
            s[nt][1] = __expf(s[nt][1] - mn0);
            s[nt][2] = __expf(s[nt][2] - mn1);
            s[nt][3] = __expf(s[nt][3] - mn1);
            sum0 += s[nt][0] + s[nt][1];
            sum1 += s[nt][2] + s[nt][3];
        }
        sum0 += __shfl_xor_sync(0xffffffffu, sum0, 1);
        sum0 += __shfl_xor_sync(0xffffffffu, sum0, 2);
        sum1 += __shfl_xor_sync(0xffffffffu, sum1, 1);
        sum1 += __shfl_xor_sync(0xffffffffu, sum1, 2);

        lrow0 = lrow0 * al0 + sum0;
        lrow1 = lrow1 * al1 + sum1;
        mrow0 = mn0; mrow1 = mn1;
        #pragma unroll
        for (int nt=0;nt<8;nt++){
            o[nt][0] *= al0; o[nt][1] *= al0;
            o[nt][2] *= al1; o[nt][3] *= al1;
        }

        // P (C-frag layout) -> smem (tf32) -> A-frag layout for PV mma.
        // Per-warp private 16-row band of Qs; warp-scope sync is sufficient.
        __syncwarp();
        #pragma unroll
        for (int nt=0;nt<8;nt++){
            const int col = nt*8 + 2*c;
            Qs[r0][sw2(r0, col)  ] = f2tf(s[nt][0]);
            Qs[r0][sw2(r0, col)+1] = f2tf(s[nt][1]);
            Qs[r1][sw2(r1, col)  ] = f2tf(s[nt][2]);
            Qs[r1][sw2(r1, col)+1] = f2tf(s[nt][3]);
        }
        __syncwarp();

        // O += P @ V
        #pragma unroll
        for (int ks=0;ks<8;ks++){
            unsigned pa[4] = {
                Qs[r0][sw2(r0, ks*8 + c)],
                Qs[r1][sw2(r1, ks*8 + c)],
                Qs[r0][sw2(r0, ks*8 + c + 4)],
                Qs[r1][sw2(r1, ks*8 + c + 4)] };
            #pragma unroll
            for (int nt=0;nt<8;nt++){
                const int rv0 = ks*8 + c, rv1 = ks*8 + c + 4;
                unsigned bb[2] = { Vs[rv0][sw3(rv0, nt*8 + g)],
                                   Vs[rv1][sw3(rv1, nt*8 + g)] };
                mma8(o[nt], pa, bb);
            }
        }
        __syncthreads();   // protect Ks/Vs before next iteration's loads
    }

    // Epilogue: O / l, write [b,t,d] layout for the output projection
    const float il0 = 1.f / lrow0, il1 = 1.f / lrow1;
    const int b = bh >> 4, h = bh & 15;
    const int r0g = qb*64 + warp*16 + g;
    float* Og = g_ao + (size_t)b * T_ * D_;
    #pragma unroll
    for (int nt=0;nt<8;nt++){
        const int col = h*64 + nt*8 + 2*c;
        *(float2*)(Og + (size_t)r0g*D_ + col)
            = make_float2(o[nt][0]*il0, o[nt][1]*il0);
        *(float2*)(Og + (size_t)(r0g+8)*D_ + col)
            = make_float2(o[nt][2]*il1, o[nt][3]*il1);
    }
}

// ---------------------------------------------------------------------------
extern "C" void kernel_launch(void* const* d_in, const int* in_sizes, int n_in,
                              void* d_out, int out_size)
{
    (void)in_sizes; (void)n_in; (void)out_size;
    const float* x  = (const float*)d_in[0];
    const float* Wq = (const float*)d_in[1];
    const float* Wk = (const float*)d_in[2];
    const float* Wv = (const float*)d_in[3];
    const float* Wo = (const float*)d_in[4];
    const float* bo = (const float*)d_in[5];

    // Fused Q/K/V projections (z selects weight), head-major epilogue
    gemm_tf32<<<dim3(8, 64, 3), 256>>>(x, Wq, Wk, Wv, nullptr, nullptr, 0);
    // Causal flash attention
    attn_tf32<<<dim3(32, 64), 128>>>();
    // Output projection + bias -> d_out
    gemm_tf32<<<dim3(8, 64, 1), 256>>>(nullptr, Wo, nullptr, nullptr,
                                       (float*)d_out, bo, 1);
}

// round 7
// speedup vs baseline: 1.1356x; 1.1356x over previous
#include <cuda_runtime.h>
#include <cstdint>

#define B_  4
#define T_  2048
#define D_  1024
#define H_  16
#define HD_ 64

// ---------------- scratch (static device globals; allocation-free) ----------
__device__ float g_q [(size_t)B_*H_*T_*HD_];   // [b,h,t,hd], tf32-exact, pre-scaled 0.125
__device__ float g_k [(size_t)B_*H_*T_*HD_];   // tf32-exact
__device__ float g_v [(size_t)B_*H_*T_*HD_];   // tf32-exact
__device__ float g_ao[(size_t)B_*T_*D_];       // attention out, [b,t,d], tf32-exact
__device__ float g_xr[(size_t)B_*T_*D_];       // RNA-rounded x
__device__ float g_wr[(size_t)4*D_*D_];        // RNA-rounded Wq,Wk,Wv,Wo

// ---------------- helpers ---------------------------------------------------
__device__ __forceinline__ unsigned f2tf(float f){
    unsigned u; asm("cvt.rna.tf32.f32 %0, %1;" : "=r"(u) : "f"(f)); return u;
}
__device__ __forceinline__ float rtf(float f){ return __uint_as_float(f2tf(f)); }

__device__ __forceinline__ uint32_t s2u(const void* p){
    uint32_t a;
    asm("{ .reg .u64 t; cvta.to.shared.u64 t, %1; cvt.u32.u64 %0, t; }" : "=r"(a) : "l"(p));
    return a;
}
__device__ __forceinline__ void cp16(uint32_t dst, const void* src){
    asm volatile("cp.async.cg.shared.global [%0], [%1], 16;" :: "r"(dst), "l"(src));
}
__device__ __forceinline__ void cp_commit(){ asm volatile("cp.async.commit_group;"); }

__device__ __forceinline__ void ldsm4(uint32_t addr, unsigned& r0, unsigned& r1,
                                      unsigned& r2, unsigned& r3){
    asm volatile("ldmatrix.sync.aligned.m8n8.x4.shared.b16 {%0,%1,%2,%3}, [%4];"
                 : "=r"(r0), "=r"(r1), "=r"(r2), "=r"(r3) : "r"(addr));
}
__device__ __forceinline__ unsigned lds32(uint32_t a){
    unsigned v; asm volatile("ld.shared.b32 %0, [%1];" : "=r"(v) : "r"(a)); return v;
}
__device__ __forceinline__ void sts64(uint32_t a, unsigned v0, unsigned v1){
    asm volatile("st.shared.v2.b32 [%0], {%1,%2};" :: "r"(a), "r"(v0), "r"(v1));
}

// m16n8k8 tf32 MMA, fp32 accumulate
__device__ __forceinline__ void mma8(float* d, const unsigned* a, const unsigned* b){
    asm volatile("mma.sync.aligned.m16n8k8.row.col.f32.tf32.tf32.f32 "
        "{%0,%1,%2,%3},{%4,%5,%6,%7},{%8,%9},{%0,%1,%2,%3};\n"
        : "+f"(d[0]), "+f"(d[1]), "+f"(d[2]), "+f"(d[3])
        : "r"(a[0]), "r"(a[1]), "r"(a[2]), "r"(a[3]), "r"(b[0]), "r"(b[1]));
}

// ---------------- pre-round pass: RNA fp32 -> tf32-exact fp32 ---------------
__global__ void __launch_bounds__(256)
preround(const float* __restrict__ x,
         const float* __restrict__ wq, const float* __restrict__ wk,
         const float* __restrict__ wv, const float* __restrict__ wo)
{
    const size_t i = ((size_t)blockIdx.x * 256 + threadIdx.x) * 4;
    const size_t NX = (size_t)B_*T_*D_;
    const size_t NW = (size_t)D_*D_;
    const float* src; float* dst; size_t off;
    if (i < NX)            { src = x;  dst = g_xr;        off = i; }
    else if (i < NX+NW)    { src = wq; dst = g_wr;        off = i - NX; }
    else if (i < NX+2*NW)  { src = wk; dst = g_wr + NW;   off = i - NX - NW; }
    else if (i < NX+3*NW)  { src = wv; dst = g_wr + 2*NW; off = i - NX - 2*NW; }
    else                   { src = wo; dst = g_wr + 3*NW; off = i - NX - 3*NW; }
    float4 v = *(const float4*)(src + off);
    v.x = rtf(v.x); v.y = rtf(v.y); v.z = rtf(v.z); v.w = rtf(v.w);
    *(float4*)(dst + off) = v;
}

// ---------------- legacy-mma tf32 GEMM, cp.async + ldmatrix ------------------
// C[m,n] = sum_k A[m,k]*B[n,k]; BM=BN=128, BK=32; 256 thr (4x2 warps, 32x64 tile)
// mode 0: A=g_xr, B per blockIdx.z; head-major out, rtf (+0.125 scale for Q).
// mode 1: A=g_ao, B=Wo; +bias -> outF [b,t,d].
#define GS_STAGE 16384
#define GB_OFF   65536
#define G_SMEM   131072

__global__ void __launch_bounds__(256, 1)
gemm_lm(const float* __restrict__ A,
        const float* __restrict__ B0, const float* __restrict__ B1,
        const float* __restrict__ B2,
        float* __restrict__ outF, const float* __restrict__ bias, int mode)
{
    extern __shared__ char smem[];
    const uint32_t sb = s2u(smem);
    const int tid = threadIdx.x, lane = tid & 31, warp = tid >> 5;
    const int g = lane >> 2, c = lane & 3;
    const int wr = warp & 3, wc = warp >> 2;
    const int m0 = blockIdx.y * 128, n0 = blockIdx.x * 128;

    const float* Bp = B0;
    if (mode == 0){ if (blockIdx.z == 1) Bp = B1; else if (blockIdx.z == 2) Bp = B2; }

    float acc[2][8][4];
    #pragma unroll
    for (int i=0;i<2;i++)
        #pragma unroll
        for (int j=0;j<8;j++)
            #pragma unroll
            for (int q2=0;q2<4;q2++) acc[i][j][q2] = 0.f;

    // cp.async fill mapping: 256 thr -> 8 chunks/row-of-128B; 4 rows each
    const int fr  = tid >> 3;          // 0..31
    const int fcb = (tid & 7) * 16;    // chunk byte
    const int fce = (tid & 7) * 4;     // chunk elem

    auto fill = [&](int s){
        const int slot = s & 3;
        const int k0 = s * 32;
        const float* sa = A  + (size_t)(m0 + fr)*D_ + k0 + fce;
        const float* sbp= Bp + (size_t)(n0 + fr)*D_ + k0 + fce;
        const uint32_t da = sb + slot*GS_STAGE;
        const uint32_t db = sb + GB_OFF + slot*GS_STAGE;
        #pragma unroll
        for (int i=0;i<4;i++){
            const int row = fr + 32*i;
            const uint32_t off = row*128 + (fcb ^ ((row & 7) << 4));
            cp16(da + off, sa + (size_t)32*i*D_);
            cp16(db + off, sbp + (size_t)32*i*D_);
        }
        cp_commit();
    };

    #pragma unroll
    for (int s=0;s<4;s++) fill(s);

    // ldmatrix lane constants
    const int aRowL  = lane & 15;            // + wr*32 + mt*16
    const int aHalf  = (lane >> 4) * 16;
    const int bRowL  = ((lane >> 4) << 3) + (lane & 7);   // + wc*64 + 16p
    const int bHalf  = ((lane >> 3) & 1) * 16;

    for (int s=0; s<32; s++){
        if (s < 28) asm volatile("cp.async.wait_group 3;");
        else        asm volatile("cp.async.wait_group 0;");
        __syncthreads();

        const uint32_t asA = sb + (s&3)*GS_STAGE;
        const uint32_t asB = sb + GB_OFF + (s&3)*GS_STAGE;

        #pragma unroll
        for (int ks=0; ks<4; ks++){
            unsigned af[2][4], bf[8][2];
            #pragma unroll
            for (int mt=0; mt<2; mt++){
                const int row = wr*32 + mt*16 + aRowL;
                const uint32_t addr = asA + row*128 + ((ks*32 + aHalf) ^ ((row&7)<<4));
                ldsm4(addr, af[mt][0], af[mt][1], af[mt][2], af[mt][3]);
            }
            #pragma unroll
            for (int p=0; p<4; p++){
                const int row = wc*64 + 16*p + bRowL;
                const uint32_t addr = asB + row*128 + ((ks*32 + bHalf) ^ ((row&7)<<4));
                ldsm4(addr, bf[2*p][0], bf[2*p][1], bf[2*p+1][0], bf[2*p+1][1]);
            }
            #pragma unroll
            for (int mt=0; mt<2; mt++)
                #pragma unroll
                for (int nt=0; nt<8; nt++)
                    mma8(acc[mt][nt], af[mt], bf[nt]);
        }
        __syncthreads();
        if (s + 4 < 32) fill(s + 4);
    }

    // epilogue
    float* outp = outF;
    float qs = 1.0f;
    if (mode == 0){
        outp = (blockIdx.z==0) ? g_q : (blockIdx.z==1) ? g_k : g_v;
        if (blockIdx.z == 0) qs = 0.125f;
    }
    #pragma unroll
    for (int mt=0; mt<2; mt++){
        #pragma unroll
        for (int half=0; half<2; half++){
            const int r = m0 + wr*32 + mt*16 + g + half*8;
            #pragma unroll
            for (int nt=0; nt<8; nt++){
                const int n = n0 + wc*64 + nt*8 + 2*c;
                const float v0 = acc[mt][nt][half*2];
                const float v1 = acc[mt][nt][half*2 + 1];
                if (mode == 0){
                    const int b = r >> 11, t = r & (T_ - 1);
                    const int h = n >> 6, hd = n & 63;
                    *(float2*)(outp + ((size_t)((b*H_ + h)*T_ + t) << 6) + hd)
                        = make_float2(rtf(v0)*qs, rtf(v1)*qs);
                } else {
                    const float2 bb = *(const float2*)(bias + n);
                    *(float2*)(outp + (size_t)r*D_ + n)
                        = make_float2(v0 + bb.x, v1 + bb.y);
                }
            }
        }
    }
}

// ---------------- causal flash attention, cp.async + ldmatrix ----------------
// 128 thr / (b,h,64-row qblock). smem: Q/P 16K | K x2 16K | V x2 16K = 80KB dyn
#define AT_SMEM 81920

__global__ void __launch_bounds__(128)
attn_tf32()
{
    extern __shared__ char smem[];
    const uint32_t sbase = s2u(smem);
    const uint32_t Qb  = sbase;
    const uint32_t Kb0 = sbase + 16384;
    const uint32_t Vb0 = sbase + 49152;

    const int qb  = blockIdx.x;
    const int bh  = blockIdx.y;
    const int tid = threadIdx.x;
    const int lane = tid & 31, warp = tid >> 5;
    const int g = lane >> 2, c = lane & 3;

    const float* Qg = g_q + (size_t)bh * (T_*HD_);
    const float* Kg = g_k + (size_t)bh * (T_*HD_);
    const float* Vg = g_v + (size_t)bh * (T_*HD_);

    // fill mapping: 128 thr -> 16 chunks per 256B row, 8 rows each
    const int fr8   = tid >> 4;          // 0..7
    const int fcb16 = (tid & 15) * 16;   // chunk byte
    const int fce   = (tid & 15) * 4;    // chunk elem

    auto fillQ = [&](){
        #pragma unroll
        for (int i=0;i<8;i++){
            const int row = fr8 + 8*i;
            const uint32_t off = row*256 + (fcb16 ^ ((row & 7) << 4));
            cp16(Qb + off, Qg + (size_t)(qb*64 + row)*64 + fce);
        }
        cp_commit();
    };
    auto fillKV = [&](int j, int buf){
        const uint32_t kb = Kb0 + buf*16384, vb = Vb0 + buf*16384;
        #pragma unroll
        for (int i=0;i<8;i++){
            const int row = fr8 + 8*i;
            const uint32_t off = row*256 + (fcb16 ^ ((row & 7) << 4));
            cp16(kb + off, Kg + (size_t)(j*64 + row)*64 + fce);
            cp16(vb + off, Vg + (size_t)(j*64 + row)*64 + fce);
        }
        cp_commit();
    };

    fillQ();
    fillKV(0, 0);
    asm volatile("cp.async.wait_group 1;");   // Q ready
    __syncthreads();

    // ldmatrix lane constants
    const int qRow   = warp*16 + (lane & 15);         // A-frag rows (Q and P)
    const int qHalf  = (lane >> 4) * 16;
    const int kRowL  = ((lane >> 4) << 3) + (lane & 7);
    const int kHalf  = ((lane >> 3) & 1) * 16;
    const uint32_t qSw = (uint32_t)((qRow & 7) << 4);

    // cache Q A-fragments (pre-scaled by 0.125 in GEMM epilogue)
    unsigned qa[8][4];
    #pragma unroll
    for (int ks=0; ks<8; ks++){
        const uint32_t addr = Qb + qRow*256 + ((ks*32 + qHalf) ^ qSw);
        ldsm4(addr, qa[ks][0], qa[ks][1], qa[ks][2], qa[ks][3]);
    }

    float o[8][4];
    #pragma unroll
    for (int nt=0;nt<8;nt++){ o[nt][0]=o[nt][1]=o[nt][2]=o[nt][3]=0.f; }
    float mrow0 = -1e30f, mrow1 = -1e30f, lrow0 = 0.f, lrow1 = 0.f;

    const int r0 = warp*16 + g, r1 = r0 + 8;

    for (int j = 0; j <= qb; j++){
        if (j < qb) fillKV(j+1, (j+1) & 1);
        if (j < qb) asm volatile("cp.async.wait_group 1;");
        else        asm volatile("cp.async.wait_group 0;");
        __syncthreads();

        const uint32_t Kb = Kb0 + (j & 1)*16384;
        const uint32_t Vb = Vb0 + (j & 1)*16384;

        // S = Qscaled @ K^T
        float s[8][4];
        #pragma unroll
        for (int nt=0;nt<8;nt++){ s[nt][0]=s[nt][1]=s[nt][2]=s[nt][3]=0.f; }
        #pragma unroll
        for (int ks=0; ks<8; ks++){
            #pragma unroll
            for (int p=0; p<4; p++){
                const int row = 16*p + kRowL;
                const uint32_t addr = Kb + row*256 + ((ks*32 + kHalf) ^ ((row&7)<<4));
                unsigned b0,b1,b2,b3;
                ldsm4(addr, b0, b1, b2, b3);
                unsigned bb0[2] = {b0, b1}, bb1[2] = {b2, b3};
                mma8(s[2*p],   qa[ks], bb0);
                mma8(s[2*p+1], qa[ks], bb1);
            }
        }

        // causal mask (diagonal block only)
        if (j == qb){
            #pragma unroll
            for (int nt=0;nt<8;nt++){
                const int col = nt*8 + 2*c;
                if (col     > r0) s[nt][0] = -1e30f;
                if (col + 1 > r0) s[nt][1] = -1e30f;
                if (col     > r1) s[nt][2] = -1e30f;
                if (col + 1 > r1) s[nt][3] = -1e30f;
            }
        }

        // online softmax
        float mx0 = -1e30f, mx1 = -1e30f;
        #pragma unroll
        for (int nt=0;nt<8;nt++){
            mx0 = fmaxf(mx0, fmaxf(s[nt][0], s[nt][1]));
            mx1 = fmaxf(mx1, fmaxf(s[nt][2], s[nt][3]));
        }
        mx0 = fmaxf(mx0, __shfl_xor_sync(0xffffffffu, mx0, 1));
        mx0 = fmaxf(mx0, __shfl_xor_sync(0xffffffffu, mx0, 2));
        mx1 = fmaxf(mx1, __shfl_xor_sync(0xffffffffu, mx1, 1));
        mx1 = fmaxf(mx1, __shfl_xor_sync(0xffffffffu, mx1, 2));

        const float mn0 = fmaxf(mrow0, mx0), mn1 = fmaxf(mrow1, mx1);
        const float al0 = __expf(mrow0 - mn0), al1 = __expf(mrow1 - mn1);
        float sum0 = 0.f, sum1 = 0.f;
        #pragma unroll
        for (int nt=0;nt<8;nt++){
            s[nt][0] = __expf(s[nt][0] - mn0);
            s[nt][1] = __expf(s[nt][1] - mn0);
            s[nt][2] = __expf(s[nt][2] - mn1);
            s[nt][3] = __expf(s[nt][3] - mn1);
            sum0 += s[nt][0] + s[nt][1];
            sum1 += s[nt][2] + s[nt][3];
        }
        sum0 += __shfl_xor_sync(0xffffffffu, sum0, 1);
        sum0 += __shfl_xor_sync(0xffffffffu, sum0, 2);
        sum1 += __shfl_xor_sync(0xffffffffu, sum1, 1);
        sum1 += __shfl_xor_sync(0xffffffffu, sum1, 2);

        lrow0 = lrow0 * al0 + sum0;
        lrow1 = lrow1 * al1 + sum1;
        mrow0 = mn0; mrow1 = mn1;
        #pragma unroll
        for (int nt=0;nt<8;nt++){
            o[nt][0] *= al0; o[nt][1] *= al0;
            o[nt][2] *= al1; o[nt][3] *= al1;
        }

        // P (tf32) -> own warp's 16-row band of the Q/P buffer
        __syncwarp();
        #pragma unroll
        for (int nt=0;nt<8;nt++){
            const int cb = nt*32 + 8*c;
            sts64(Qb + r0*256 + (cb ^ ((uint32_t)g << 4)), f2tf(s[nt][0]), f2tf(s[nt][1]));
            sts64(Qb + r1*256 + (cb ^ ((uint32_t)g << 4)), f2tf(s[nt][2]), f2tf(s[nt][3]));
        }
        __syncwarp();

        // O += P @ V
        #pragma unroll
        for (int ks=0; ks<8; ks++){
            unsigned pa[4];
            const uint32_t paddr = Qb + qRow*256 + ((ks*32 + qHalf) ^ qSw);
            ldsm4(paddr, pa[0], pa[1], pa[2], pa[3]);
            const int rv0 = ks*8 + c, rv1 = rv0 + 4;
            const uint32_t vb0 = Vb + rv0*256, sw0 = (uint32_t)c << 4;
            const uint32_t vb1 = Vb + rv1*256, sw1 = (uint32_t)(c + 4) << 4;
            #pragma unroll
            for (int nt=0; nt<8; nt++){
                const int col4 = nt*32 + g*4;
                unsigned bb[2] = { lds32(vb0 + (col4 ^ sw0)),
                                   lds32(vb1 + (col4 ^ sw1)) };
                mma8(o[nt], pa, bb);
            }
        }
        __syncthreads();
    }

    // epilogue: O/l, tf32-rounded (O-projection consumes it truncation-free)
    const float il0 = 1.f / lrow0, il1 = 1.f / lrow1;
    const int b = bh >> 4, h = bh & 15;
    const int r0g = qb*64 + warp*16 + g;
    float* Og = g_ao + (size_t)b * T_ * D_;
    #pragma unroll
    for (int nt=0;nt<8;nt++){
        const int col = h*64 + nt*8 + 2*c;
        *(float2*)(Og + (size_t)r0g*D_ + col)
            = make_float2(rtf(o[nt][0]*il0), rtf(o[nt][1]*il0));
        *(float2*)(Og + (size_t)(r0g+8)*D_ + col)
            = make_float2(rtf(o[nt][2]*il1), rtf(o[nt][3]*il1));
    }
}

// ---------------------------------------------------------------------------
extern "C" void kernel_launch(void* const* d_in, const int* in_sizes, int n_in,
                              void* d_out, int out_size)
{
    (void)in_sizes; (void)n_in; (void)out_size;
    const float* x  = (const float*)d_in[0];
    const float* Wq = (const float*)d_in[1];
    const float* Wk = (const float*)d_in[2];
    const float* Wv = (const float*)d_in[3];
    const float* Wo = (const float*)d_in[4];
    const float* bo = (const float*)d_in[5];

    cudaFuncSetAttribute(gemm_lm, cudaFuncAttributeMaxDynamicSharedMemorySize, G_SMEM);
    cudaFuncSetAttribute(attn_tf32, cudaFuncAttributeMaxDynamicSharedMemorySize, AT_SMEM);

    const size_t NW = (size_t)D_*D_;
    float* wr; cudaGetSymbolAddress((void**)&wr, g_wr);
    float* xr; cudaGetSymbolAddress((void**)&xr, g_xr);
    float* ao; cudaGetSymbolAddress((void**)&ao, g_ao);

    // 1) RNA pre-round (hot loops then need no conversions at all)
    preround<<<12288, 256>>>(x, Wq, Wk, Wv, Wo);

    // 2) fused Q/K/V projections -> head-major tf32-exact scratch
    gemm_lm<<<dim3(8, 64, 3), 256, G_SMEM>>>(xr, wr, wr + NW, wr + 2*NW,
                                             nullptr, nullptr, 0);
    // 3) causal flash attention
    attn_tf32<<<dim3(32, 64), 128, AT_SMEM>>>();

    // 4) output projection + bias -> d_out
    gemm_lm<<<dim3(8, 64, 1), 256, G_SMEM>>>(ao, wr + 3*NW, nullptr, nullptr,
                                             (float*)d_out, bo, 1);
}